// round 6
// baseline (speedup 1.0000x reference)
#include <cuda_runtime.h>
#include <math.h>

#define BN 16
#define HH 480
#define WW 640
#define HW (HH * WW)
#define HW4 (HW / 4)              // 76800 float4 per plane
#define W4 (WW / 4)               // 160 float4 per row
#define TOTAL (BN * HW4)          // 1228800 quads
#define TPB 256
#define NBLK 592                  // 148 SMs * 4 CTAs, single balanced wave
#define GSTRIDE (NBLK * TPB)      // 151552

// Allocation-free scratch.
__device__ float g_partials[NBLK];
__device__ unsigned int g_count = 0;

// Exact GELU, fast path: for |z| >= 16, z*Phi(z) == max(z,0) to <1e-50 abs.
__device__ __forceinline__ float gelu_exact(float z) {
    float val = fmaxf(z, 0.0f);
    if (fabsf(z) < 16.0f) val = z * normcdff(z);
    return val;
}

struct IterData {
    float4 g0, g1, n0, n1;
    float V0, V1, V2, O0, O1, O2;
};

__device__ __forceinline__ void load_iter(
    int q, const float* __restrict__ pose,
    const float* __restrict__ grad, const float* __restrict__ nf,
    IterData& d)
{
    const int b = q / HW4;                 // const divisor -> mul/shift
    const int i = q - b * HW4;

    const float4* __restrict__ gp = (const float4*)grad + (size_t)b * 2 * HW4;
    const float4* __restrict__ np = (const float4*)nf   + (size_t)b * 2 * HW4;

    d.g0 = gp[i];
    d.g1 = gp[i + HW4];
    d.n0 = np[i];
    d.n1 = np[i + HW4];

    d.V0 = __ldg(pose + b * 6 + 0);
    d.V1 = __ldg(pose + b * 6 + 1);
    d.V2 = __ldg(pose + b * 6 + 2);
    d.O0 = __ldg(pose + b * 6 + 3);
    d.O1 = __ldg(pose + b * 6 + 4);
    d.O2 = __ldg(pose + b * 6 + 5);
}

__device__ __forceinline__ float compute_iter(int q, const IterData& d)
{
    const int b = q / HW4;
    const int i = q - b * HW4;
    const int h = i / W4;
    const float x0 = (float)((i - h * W4) * 4);
    const float y  = (float)h;

    const float AV1    = fmaf(y, d.V2, -d.V1);         // -V1 + y*V2
    const float yO2    = y * d.O2;
    const float y2p1O0 = fmaf(y, y, 1.0f) * d.O0;      // (y^2+1)*O0
    const float yO0    = y * d.O0;
    const float yO1    = y * d.O1;

    const float* ga = &d.g0.x;
    const float* gb = &d.g1.x;
    const float* na = &d.n0.x;
    const float* nb = &d.n1.x;

    float s4 = 0.0f;
    #pragma unroll
    for (int j = 0; j < 4; j++) {
        const float x = x0 + (float)j;

        const float AV0 = fmaf(x, d.V2, -d.V0);                       // -V0 + x*V2
        // BW0 = x*(y*O0) - (x^2+1)*O1 + y*O2
        const float BW0 = fmaf(x, yO0, fmaf(-fmaf(x, x, 1.0f), d.O1, yO2));
        // BW1 = (y^2+1)*O0 - x*(y*O1) - x*O2
        const float BW1 = fmaf(-x, yO1, fmaf(-x, d.O2, y2p1O0));

        const float gg0 = ga[j], gg1 = gb[j];
        const float s = fmaf(gg0, AV0, gg1 * AV1);
        const float t = (na[j] + nb[j]) - fmaf(gg0, BW0, gg1 * BW1);
        s4 += gelu_exact(-(s * t));
    }
    return s4;
}

__global__ __launch_bounds__(TPB, 4) void cheirality_fused(
    const float* __restrict__ pose,
    const float* __restrict__ grad,
    const float* __restrict__ nf,
    float* __restrict__ out)
{
    const int tid = threadIdx.x;
    const int t   = blockIdx.x * TPB + tid;   // t < 151552 <= TOTAL: prologue safe

    float acc = 0.0f;

    // Software-pipelined flat grid-stride: load iter k+1 before computing k.
    int q = t;
    IterData cur;
    load_iter(q, pose, grad, nf, cur);

    for (int qn = q + GSTRIDE; qn < TOTAL; qn += GSTRIDE) {
        IterData nxt;
        load_iter(qn, pose, grad, nf, nxt);
        acc += compute_iter(q, cur);
        q = qn;
        cur = nxt;
    }
    acc += compute_iter(q, cur);

    // ---- block reduction (float tree) ----
    __shared__ float warp_sums[TPB / 32];
    __shared__ bool  is_last;
    const unsigned mask = 0xFFFFFFFFu;
    #pragma unroll
    for (int off = 16; off > 0; off >>= 1)
        acc += __shfl_down_sync(mask, acc, off);

    const int lane = tid & 31;
    const int wid  = tid >> 5;
    if (lane == 0) warp_sums[wid] = acc;
    __syncthreads();

    if (tid == 0) {
        float bsum = 0.0f;
        #pragma unroll
        for (int w = 0; w < TPB / 32; w++) bsum += warp_sums[w];
        g_partials[blockIdx.x] = bsum;
        __threadfence();
        unsigned int old = atomicAdd(&g_count, 1u);
        is_last = (old == (unsigned)(NBLK - 1));
    }
    __syncthreads();

    // ---- last block: sum partials in double, write scalar ----
    if (is_last) {
        double v = 0.0;
        for (int p = tid; p < NBLK; p += TPB)
            v += (double)g_partials[p];

        __shared__ double dsums[TPB / 32];
        #pragma unroll
        for (int off = 16; off > 0; off >>= 1)
            v += __shfl_down_sync(mask, v, off);
        if (lane == 0) dsums[wid] = v;
        __syncthreads();

        if (tid == 0) {
            double total = 0.0;
            #pragma unroll
            for (int w = 0; w < TPB / 32; w++) total += dsums[w];
            out[0] = (float)(total / (double)((long long)BN * HW));
            g_count = 0;   // reset for next graph replay
        }
    }
}

extern "C" void kernel_launch(void* const* d_in, const int* in_sizes, int n_in,
                              void* d_out, int out_size) {
    const float* pose = (const float*)d_in[0];
    const float* grad = (const float*)d_in[1];
    const float* nf   = (const float*)d_in[2];
    float* out = (float*)d_out;

    cheirality_fused<<<NBLK, TPB>>>(pose, grad, nf, out);
}

// round 7
// speedup vs baseline: 1.1379x; 1.1379x over previous
#include <cuda_runtime.h>
#include <math.h>

#define BN 16
#define HH 480
#define WW 640
#define HW (HH * WW)
#define HW4 (HW / 4)            // 76800 float4 per plane
#define W4 (WW / 4)             // 160 float4 per row
#define GX 37
#define TPB 256
#define NBLK (GX * BN)          // 592 = 148 SMs * 4 CTAs, single balanced wave
#define STRIDE4 (GX * TPB)      // 9472
#define MAIN_ITERS 8            // 8*9472 = 75776 quads per plane
#define MAIN_Q (MAIN_ITERS * STRIDE4)   // 75776
#define TAIL_Q (HW4 - MAIN_Q)   // 1024 quads per plane
#define TAIL_TOTAL (BN * TAIL_Q) // 16384

// Allocation-free scratch.
__device__ float g_partials[NBLK];
__device__ unsigned int g_count = 0;

// Exact GELU, fast path: for |z| >= 16, z*Phi(z) == max(z,0) to <1e-50 abs.
__device__ __forceinline__ float gelu_exact(float z) {
    float val = fmaxf(z, 0.0f);
    if (fabsf(z) < 16.0f) val = z * normcdff(z);
    return val;
}

__device__ __forceinline__ float quad_sum(
    float4 g0, float4 g1, float4 n0, float4 n1, int i,
    float V0, float V1, float V2, float O0, float O1, float O2)
{
    const int   h  = i / W4;                 // const divisor -> mul/shift
    const float x0 = (float)((i - h * W4) * 4);
    const float y  = (float)h;

    const float AV1    = fmaf(y, V2, -V1);          // -V1 + y*V2
    const float yO2    = y * O2;
    const float y2p1O0 = fmaf(y, y, 1.0f) * O0;     // (y^2+1)*O0
    const float yO0    = y * O0;
    const float yO1    = y * O1;

    const float* ga = &g0.x;
    const float* gb = &g1.x;
    const float* na = &n0.x;
    const float* nb = &n1.x;

    float s4 = 0.0f;
    #pragma unroll
    for (int j = 0; j < 4; j++) {
        const float x = x0 + (float)j;

        const float AV0 = fmaf(x, V2, -V0);                        // -V0 + x*V2
        // BW0 = x*(y*O0) - (x^2+1)*O1 + y*O2
        const float BW0 = fmaf(x, yO0, fmaf(-fmaf(x, x, 1.0f), O1, yO2));
        // BW1 = (y^2+1)*O0 - x*(y*O1) - x*O2
        const float BW1 = fmaf(-x, yO1, fmaf(-x, O2, y2p1O0));

        const float gg0 = ga[j], gg1 = gb[j];
        const float s = fmaf(gg0, AV0, gg1 * AV1);
        const float t = (na[j] + nb[j]) - fmaf(gg0, BW0, gg1 * BW1);
        s4 += gelu_exact(-(s * t));
    }
    return s4;
}

__global__ __launch_bounds__(TPB, 4) void cheirality_fused(
    const float* __restrict__ pose,
    const float* __restrict__ grad,
    const float* __restrict__ nf,
    float* __restrict__ out)
{
    const int b   = blockIdx.y;
    const int tid = threadIdx.x;

    const float V0 = __ldg(pose + b * 6 + 0);
    const float V1 = __ldg(pose + b * 6 + 1);
    const float V2 = __ldg(pose + b * 6 + 2);
    const float O0 = __ldg(pose + b * 6 + 3);
    const float O1 = __ldg(pose + b * 6 + 4);
    const float O2 = __ldg(pose + b * 6 + 5);

    const float4* __restrict__ g0p = (const float4*)(grad + (size_t)b * 2 * HW);
    const float4* __restrict__ g1p = g0p + HW4;
    const float4* __restrict__ n0p = (const float4*)(nf + (size_t)b * 2 * HW);
    const float4* __restrict__ n1p = n0p + HW4;

    const int i0 = blockIdx.x * TPB + tid;   // 0..9471

    float acc = 0.0f;

    // ---- main loop: exactly 8 pipelined, fully unrolled iterations ----
    int i = i0;
    float4 g0 = g0p[i], g1 = g1p[i], n0 = n0p[i], n1 = n1p[i];

    #pragma unroll
    for (int k = 1; k < MAIN_ITERS; k++) {
        const int inext = i0 + k * STRIDE4;
        float4 g0n = g0p[inext];
        float4 g1n = g1p[inext];
        float4 n0n = n0p[inext];
        float4 n1n = n1p[inext];

        acc += quad_sum(g0, g1, n0, n1, i, V0, V1, V2, O0, O1, O2);

        i = inext;
        g0 = g0n; g1 = g1n; n0 = n0n; n1 = n1n;
    }
    acc += quad_sum(g0, g1, n0, n1, i, V0, V1, V2, O0, O1, O2);

    // ---- distributed tail: 16384 leftover quads, flat thread ids 0..16383 ----
    // These are CTAs bid 0..63 -> 64 distinct SMs, +1 quad per thread there.
    const int ft = (b * GX + blockIdx.x) * TPB + tid;
    if (ft < TAIL_TOTAL) {
        const int tb = ft / TAIL_Q;                  // plane (const divisor)
        const int ti = MAIN_Q + (ft - tb * TAIL_Q);  // quad index in plane

        const float4* __restrict__ tg = (const float4*)(grad + (size_t)tb * 2 * HW);
        const float4* __restrict__ tn = (const float4*)(nf   + (size_t)tb * 2 * HW);
        float4 tg0 = tg[ti], tg1 = tg[ti + HW4];
        float4 tn0 = tn[ti], tn1 = tn[ti + HW4];

        const float tV0 = __ldg(pose + tb * 6 + 0);
        const float tV1 = __ldg(pose + tb * 6 + 1);
        const float tV2 = __ldg(pose + tb * 6 + 2);
        const float tO0 = __ldg(pose + tb * 6 + 3);
        const float tO1 = __ldg(pose + tb * 6 + 4);
        const float tO2 = __ldg(pose + tb * 6 + 5);

        acc += quad_sum(tg0, tg1, tn0, tn1, ti, tV0, tV1, tV2, tO0, tO1, tO2);
    }

    // ---- block reduction (float tree) ----
    __shared__ float warp_sums[TPB / 32];
    __shared__ bool  is_last;
    const unsigned mask = 0xFFFFFFFFu;
    #pragma unroll
    for (int off = 16; off > 0; off >>= 1)
        acc += __shfl_down_sync(mask, acc, off);

    const int lane = tid & 31;
    const int wid  = tid >> 5;
    if (lane == 0) warp_sums[wid] = acc;
    __syncthreads();

    if (tid == 0) {
        float bsum = 0.0f;
        #pragma unroll
        for (int w = 0; w < TPB / 32; w++) bsum += warp_sums[w];
        g_partials[blockIdx.y * GX + blockIdx.x] = bsum;
        __threadfence();
        unsigned int old = atomicAdd(&g_count, 1u);
        is_last = (old == (unsigned)(NBLK - 1));
    }
    __syncthreads();

    // ---- last block: sum partials in double, write scalar ----
    if (is_last) {
        double v = 0.0;
        for (int p = tid; p < NBLK; p += TPB)
            v += (double)g_partials[p];

        __shared__ double dsums[TPB / 32];
        #pragma unroll
        for (int off = 16; off > 0; off >>= 1)
            v += __shfl_down_sync(mask, v, off);
        if (lane == 0) dsums[wid] = v;
        __syncthreads();

        if (tid == 0) {
            double total = 0.0;
            #pragma unroll
            for (int w = 0; w < TPB / 32; w++) total += dsums[w];
            out[0] = (float)(total / (double)((long long)BN * HW));
            g_count = 0;   // reset for next graph replay
        }
    }
}

extern "C" void kernel_launch(void* const* d_in, const int* in_sizes, int n_in,
                              void* d_out, int out_size) {
    const float* pose = (const float*)d_in[0];
    const float* grad = (const float*)d_in[1];
    const float* nf   = (const float*)d_in[2];
    float* out = (float*)d_out;

    dim3 grid(GX, BN);
    cheirality_fused<<<grid, TPB>>>(pose, grad, nf, out);
}